// round 1
// baseline (speedup 1.0000x reference)
#include <cuda_runtime.h>
#include <math.h>
#include <stdint.h>

#define BATCH 2
#define SEQ   2048
#define DIM   1024
#define HEADS 16
#define DH    64
#define INNER 1024

// ---------------- scratch (device globals; no allocs) ----------------
__device__ float g_h  [BATCH*SEQ*DIM];            // LN output  (B,N,DIM)
__device__ float g_qkv[BATCH*3*INNER*SEQ];        // (B, 3*INNER, SEQ) channel-major
__device__ float g_q  [BATCH*INNER*SEQ];          // (B, INNER, SEQ) channel-major (scaled)
__device__ float g_k  [BATCH*INNER*SEQ];
__device__ float g_v  [BATCH*INNER*SEQ];
__device__ float g_ao [BATCH*SEQ*INNER];          // attention out (B,N,INNER)

// ---------------- LayerNorm ----------------
__global__ __launch_bounds__(256) void ln_kernel(const float* __restrict__ x,
                                                 const float* __restrict__ gamma,
                                                 const float* __restrict__ beta) {
    int row = blockIdx.x;              // 0..B*SEQ-1
    int tid = threadIdx.x;             // 256 threads, 4 floats each = 1024
    const float4* xr = reinterpret_cast<const float4*>(x) + (size_t)row * (DIM/4);
    float4 t = xr[tid];
    float s  = t.x + t.y + t.z + t.w;
    float ss = t.x*t.x + t.y*t.y + t.z*t.z + t.w*t.w;
    #pragma unroll
    for (int o = 16; o > 0; o >>= 1) {
        s  += __shfl_xor_sync(0xffffffffu, s,  o);
        ss += __shfl_xor_sync(0xffffffffu, ss, o);
    }
    __shared__ float ws[8], wss[8];
    int w = tid >> 5, l = tid & 31;
    if (l == 0) { ws[w] = s; wss[w] = ss; }
    __syncthreads();
    if (w == 0) {
        float a = (l < 8) ? ws[l]  : 0.f;
        float b = (l < 8) ? wss[l] : 0.f;
        #pragma unroll
        for (int o = 4; o > 0; o >>= 1) {
            a += __shfl_xor_sync(0xffffffffu, a, o);
            b += __shfl_xor_sync(0xffffffffu, b, o);
        }
        if (l == 0) { ws[0] = a; wss[0] = b; }
    }
    __syncthreads();
    float mu  = ws[0]  * (1.f / DIM);
    float var = wss[0] * (1.f / DIM) - mu * mu;
    float r   = rsqrtf(var + 1e-5f);
    float4 gm = reinterpret_cast<const float4*>(gamma)[tid];
    float4 bt = reinterpret_cast<const float4*>(beta)[tid];
    float4 o;
    o.x = (t.x - mu) * r * gm.x + bt.x;
    o.y = (t.y - mu) * r * gm.y + bt.y;
    o.z = (t.z - mu) * r * gm.z + bt.z;
    o.w = (t.w - mu) * r * gm.w + bt.w;
    reinterpret_cast<float4*>(g_h)[(size_t)row * (DIM/4) + tid] = o;
}

// ---------------- generic GEMM-NT: C[m][n] = sum_k A[m][k]*B[n][k] ----------------
// BM=BN=128, BK=16, 256 threads, 8x8 microtile per thread. Dims must divide tiles.
__global__ __launch_bounds__(256) void gemm_nt(const float* __restrict__ A,
                                               const float* __restrict__ B,
                                               float* __restrict__ C,
                                               int M, int N, int K,
                                               long strideB, long strideC) {
    __shared__ __align__(16) float As[16 * 132];
    __shared__ __align__(16) float Bs[16 * 132];
    const float* Bz = B + (size_t)blockIdx.z * strideB;
    float*       Cz = C + (size_t)blockIdx.z * strideC;
    int m0 = blockIdx.y * 128, n0 = blockIdx.x * 128;
    int tid = threadIdx.x;
    int ty = tid >> 4, tx = tid & 15;
    float acc[8][8] = {};
    for (int k0 = 0; k0 < K; k0 += 16) {
        #pragma unroll
        for (int i = 0; i < 2; i++) {
            int f = tid + 256 * i;          // 0..511
            int r = f >> 2, kq = f & 3;
            float4 a = *reinterpret_cast<const float4*>(A  + (size_t)(m0 + r) * K + k0 + kq * 4);
            As[(kq*4+0)*132 + r] = a.x;
            As[(kq*4+1)*132 + r] = a.y;
            As[(kq*4+2)*132 + r] = a.z;
            As[(kq*4+3)*132 + r] = a.w;
            float4 b = *reinterpret_cast<const float4*>(Bz + (size_t)(n0 + r) * K + k0 + kq * 4);
            Bs[(kq*4+0)*132 + r] = b.x;
            Bs[(kq*4+1)*132 + r] = b.y;
            Bs[(kq*4+2)*132 + r] = b.z;
            Bs[(kq*4+3)*132 + r] = b.w;
        }
        __syncthreads();
        #pragma unroll
        for (int kk = 0; kk < 16; kk++) {
            float a[8], b[8];
            *reinterpret_cast<float4*>(&a[0]) = *reinterpret_cast<float4*>(&As[kk*132 + ty*8]);
            *reinterpret_cast<float4*>(&a[4]) = *reinterpret_cast<float4*>(&As[kk*132 + ty*8 + 4]);
            *reinterpret_cast<float4*>(&b[0]) = *reinterpret_cast<float4*>(&Bs[kk*132 + tx*8]);
            *reinterpret_cast<float4*>(&b[4]) = *reinterpret_cast<float4*>(&Bs[kk*132 + tx*8 + 4]);
            #pragma unroll
            for (int ii = 0; ii < 8; ii++)
                #pragma unroll
                for (int jj = 0; jj < 8; jj++)
                    acc[ii][jj] += a[ii] * b[jj];
        }
        __syncthreads();
    }
    #pragma unroll
    for (int ii = 0; ii < 8; ii++) {
        float4 v0 = make_float4(acc[ii][0], acc[ii][1], acc[ii][2], acc[ii][3]);
        float4 v1 = make_float4(acc[ii][4], acc[ii][5], acc[ii][6], acc[ii][7]);
        float* cp = Cz + (size_t)(m0 + ty*8 + ii) * N + n0 + tx*8;
        *reinterpret_cast<float4*>(cp)     = v0;
        *reinterpret_cast<float4*>(cp + 4) = v1;
    }
}

// ---------------- depthwise causal conv (channel-major in/out) ----------------
// p selects q/k/v source slice + destination; q applies 1/sqrt(64).
__global__ __launch_bounds__(256) void conv_kernel(int p,
    const float* __restrict__ w3, const float* __restrict__ b3,
    const float* __restrict__ w5, const float* __restrict__ b5,
    const float* __restrict__ w7, const float* __restrict__ b7) {
    int idx = blockIdx.x * 256 + threadIdx.x;     // B*INNER*SEQ threads
    int n = idx & (SEQ - 1);
    int c = (idx >> 11) & (INNER - 1);
    int b = idx >> 21;
    const float* row = g_qkv + ((size_t)b * 3 * INNER + (size_t)p * INNER + c) * SEQ;
    int g = c >> 8, cg = c & 255;
    float acc;
    if (g == 0) {
        acc = row[n];
    } else {
        int ksz = 2 * g + 1;                      // 3,5,7
        const float* w  = (g == 1 ? w3 : (g == 2 ? w5 : w7)) + cg * ksz;
        const float* bb = (g == 1 ? b3 : (g == 2 ? b5 : b7));
        acc = bb[cg];
        for (int t = 0; t < ksz; t++) {
            int m = n - (ksz - 1) + t;
            if (m >= 0) acc += w[t] * row[m];
        }
    }
    float scale = (p == 0) ? 0.125f : 1.0f;       // 64^-0.5
    float* dst = (p == 0 ? g_q : (p == 1 ? g_k : g_v));
    dst[((size_t)b * INNER + c) * SEQ + n] = acc * scale;
}

// ---------------- flash-style causal attention with ALiBi ----------------
// Q/K/V in (B,H,Dh,N) channel-major. 64x64 tiles, 256 threads.
__global__ __launch_bounds__(256) void attn_kernel(const float* __restrict__ slopes) {
    extern __shared__ float sm[];
    float* Qs   = sm;                 // [d][r]  64x68
    float* Ks   = Qs  + 64*68;        // [d][n]
    float* Vs   = Ks  + 64*68;        // [n][d]
    float* Ssm  = Vs  + 64*68;        // [r][n]
    float* Pt   = Ssm + 64*68;        // [n][r]
    float* row_m  = Pt + 64*68;
    float* row_l  = row_m + 64;
    float* row_sc = row_l + 64;

    int it = blockIdx.x; int i0 = it * 64;
    int bh = blockIdx.y; int b = bh >> 4, h = bh & 15;
    float slope = slopes[h];
    int tid = threadIdx.x;
    int ty = tid >> 4, tx = tid & 15;
    const float* Qb = g_q + (size_t)bh * DH * SEQ;
    const float* Kb = g_k + (size_t)bh * DH * SEQ;
    const float* Vb = g_v + (size_t)bh * DH * SEQ;

    #pragma unroll
    for (int i = 0; i < 4; i++) {               // load Q tile (once)
        int f = tid + 256 * i;                  // 0..1023
        int d = f >> 4, c4 = f & 15;
        float4 v = *reinterpret_cast<const float4*>(Qb + (size_t)d * SEQ + i0 + c4 * 4);
        *reinterpret_cast<float4*>(&Qs[d*68 + c4*4]) = v;
    }
    if (tid < 64) { row_m[tid] = -3.4e38f; row_l[tid] = 0.f; }
    float o[4][4] = {};
    __syncthreads();

    for (int jt = 0; jt <= it; jt++) {
        int j0 = jt * 64;
        #pragma unroll
        for (int i = 0; i < 4; i++) {           // load K (direct), V (transposed)
            int f = tid + 256 * i;
            int d = f >> 4, c4 = f & 15;
            float4 kv = *reinterpret_cast<const float4*>(Kb + (size_t)d * SEQ + j0 + c4 * 4);
            *reinterpret_cast<float4*>(&Ks[d*68 + c4*4]) = kv;
            float4 vv = *reinterpret_cast<const float4*>(Vb + (size_t)d * SEQ + j0 + c4 * 4);
            Vs[(c4*4+0)*68 + d] = vv.x;
            Vs[(c4*4+1)*68 + d] = vv.y;
            Vs[(c4*4+2)*68 + d] = vv.z;
            Vs[(c4*4+3)*68 + d] = vv.w;
        }
        __syncthreads();

        float s[4][4] = {};                     // S = Q K^T (outer product over d)
        #pragma unroll 8
        for (int kk = 0; kk < 64; kk++) {
            float4 a  = *reinterpret_cast<float4*>(&Qs[kk*68 + ty*4]);
            float4 bb = *reinterpret_cast<float4*>(&Ks[kk*68 + tx*4]);
            float av[4] = {a.x, a.y, a.z, a.w};
            float bw[4] = {bb.x, bb.y, bb.z, bb.w};
            #pragma unroll
            for (int ii = 0; ii < 4; ii++)
                #pragma unroll
                for (int jj = 0; jj < 4; jj++)
                    s[ii][jj] += av[ii] * bw[jj];
        }
        #pragma unroll
        for (int ii = 0; ii < 4; ii++)
            #pragma unroll
            for (int jj = 0; jj < 4; jj++) {
                int i = i0 + ty*4 + ii, j = j0 + tx*4 + jj;
                float val = s[ii][jj] + slope * (float)(j - i);
                if (j > i) val = -3.4e38f;
                Ssm[(ty*4+ii)*68 + tx*4 + jj] = val;
            }
        __syncthreads();

        {                                       // online softmax: 4 threads per row
            int r = tid >> 2, q = tid & 3;
            float p[16];
            *reinterpret_cast<float4*>(&p[0])  = *reinterpret_cast<float4*>(&Ssm[r*68 + q*16 + 0]);
            *reinterpret_cast<float4*>(&p[4])  = *reinterpret_cast<float4*>(&Ssm[r*68 + q*16 + 4]);
            *reinterpret_cast<float4*>(&p[8])  = *reinterpret_cast<float4*>(&Ssm[r*68 + q*16 + 8]);
            *reinterpret_cast<float4*>(&p[12]) = *reinterpret_cast<float4*>(&Ssm[r*68 + q*16 + 12]);
            float mloc = p[0];
            #pragma unroll
            for (int t = 1; t < 16; t++) mloc = fmaxf(mloc, p[t]);
            mloc = fmaxf(mloc, __shfl_xor_sync(0xffffffffu, mloc, 1));
            mloc = fmaxf(mloc, __shfl_xor_sync(0xffffffffu, mloc, 2));
            float m_old = row_m[r];
            float m_new = fmaxf(m_old, mloc);
            float sum = 0.f;
            #pragma unroll
            for (int t = 0; t < 16; t++) { p[t] = __expf(p[t] - m_new); sum += p[t]; }
            sum += __shfl_xor_sync(0xffffffffu, sum, 1);
            sum += __shfl_xor_sync(0xffffffffu, sum, 2);
            float sc = __expf(m_old - m_new);
            if (q == 0) { row_m[r] = m_new; row_l[r] = row_l[r] * sc + sum; row_sc[r] = sc; }
            #pragma unroll
            for (int t = 0; t < 16; t++) Pt[(q*16 + t)*68 + r] = p[t];
        }
        __syncthreads();

        #pragma unroll
        for (int ii = 0; ii < 4; ii++) {        // rescale accumulators
            float sc = row_sc[ty*4 + ii];
            #pragma unroll
            for (int jj = 0; jj < 4; jj++) o[ii][jj] *= sc;
        }
        #pragma unroll 8
        for (int n = 0; n < 64; n++) {          // O += P V (outer product over n)
            float4 a = *reinterpret_cast<float4*>(&Pt[n*68 + ty*4]);
            float4 v = *reinterpret_cast<float4*>(&Vs[n*68 + tx*4]);
            float av[4] = {a.x, a.y, a.z, a.w};
            float vw[4] = {v.x, v.y, v.z, v.w};
            #pragma unroll
            for (int ii = 0; ii < 4; ii++)
                #pragma unroll
                for (int jj = 0; jj < 4; jj++)
                    o[ii][jj] += av[ii] * vw[jj];
        }
        __syncthreads();
    }

    #pragma unroll
    for (int ii = 0; ii < 4; ii++) {            // normalize + write (B,N,INNER)
        int r = ty*4 + ii;
        float inv = 1.f / row_l[r];
        float4 v = make_float4(o[ii][0]*inv, o[ii][1]*inv, o[ii][2]*inv, o[ii][3]*inv);
        *reinterpret_cast<float4*>(&g_ao[((size_t)b * SEQ + i0 + r) * INNER + h*DH + tx*4]) = v;
    }
}

// ---------------- launch ----------------
extern "C" void kernel_launch(void* const* d_in, const int* in_sizes, int n_in,
                              void* d_out, int out_size) {
    const float* x      = (const float*)d_in[0];
    const float* gamma  = (const float*)d_in[1];
    const float* beta   = (const float*)d_in[2];
    const float* w_qkv  = (const float*)d_in[3];
    const float* slopes = (const float*)d_in[22];
    const float* w_out  = (const float*)d_in[23];

    float *ph, *pqkv, *pao;
    cudaGetSymbolAddress((void**)&ph,   g_h);
    cudaGetSymbolAddress((void**)&pqkv, g_qkv);
    cudaGetSymbolAddress((void**)&pao,  g_ao);

    // 1) LayerNorm
    ln_kernel<<<BATCH * SEQ, 256>>>(x, gamma, beta);

    // 2) QKV GEMM: per batch, C(3072 x 2048) = W(3072x1024) . H_b^T
    gemm_nt<<<dim3(SEQ/128, 3*INNER/128, BATCH), 256>>>(
        w_qkv, ph, pqkv, 3*INNER, SEQ, DIM,
        (long)SEQ * DIM, (long)3 * INNER * SEQ);

    // 3) depthwise causal convs (q scaled by 1/8)
    int convBlocks = (BATCH * INNER * SEQ) / 256;
    conv_kernel<<<convBlocks, 256>>>(0,
        (const float*)d_in[4],  (const float*)d_in[5],
        (const float*)d_in[6],  (const float*)d_in[7],
        (const float*)d_in[8],  (const float*)d_in[9]);
    conv_kernel<<<convBlocks, 256>>>(1,
        (const float*)d_in[10], (const float*)d_in[11],
        (const float*)d_in[12], (const float*)d_in[13],
        (const float*)d_in[14], (const float*)d_in[15]);
    conv_kernel<<<convBlocks, 256>>>(2,
        (const float*)d_in[16], (const float*)d_in[17],
        (const float*)d_in[18], (const float*)d_in[19],
        (const float*)d_in[20], (const float*)d_in[21]);

    // 4) attention
    size_t smem = (size_t)(5 * 64 * 68 + 3 * 64) * sizeof(float);  // 87808 B
    cudaFuncSetAttribute(attn_kernel, cudaFuncAttributeMaxDynamicSharedMemorySize, (int)smem);
    attn_kernel<<<dim3(SEQ/64, BATCH*HEADS), 256, smem>>>(slopes);

    // 5) output projection: C(4096 x 1024) = AO(4096x1024) . Wout^T
    gemm_nt<<<dim3(DIM/128, (BATCH*SEQ)/128, 1), 256>>>(
        pao, w_out, (float*)d_out, BATCH*SEQ, DIM, INNER, 0, 0);
}

// round 2
// speedup vs baseline: 1.4986x; 1.4986x over previous
#include <cuda_runtime.h>
#include <math.h>
#include <stdint.h>

#define BATCH 2
#define SEQ   2048
#define DIM   1024
#define HEADS 16
#define DH    64
#define INNER 1024

// ---------------- scratch (device globals; no allocs) ----------------
__device__ float g_h  [BATCH*SEQ*DIM];            // LN output  (B,N,DIM)
__device__ float g_qkv[BATCH*3*INNER*SEQ];        // (B, 3*INNER, SEQ) channel-major
__device__ float g_q  [BATCH*INNER*SEQ];          // (B, INNER, SEQ) channel-major (scaled)
__device__ float g_k  [BATCH*INNER*SEQ];
__device__ float g_v  [BATCH*INNER*SEQ];
__device__ float g_ao [BATCH*SEQ*INNER];          // attention out (B,N,INNER)

// ---------------- LayerNorm ----------------
__global__ __launch_bounds__(256) void ln_kernel(const float* __restrict__ x,
                                                 const float* __restrict__ gamma,
                                                 const float* __restrict__ beta) {
    int row = blockIdx.x;              // 0..B*SEQ-1
    int tid = threadIdx.x;             // 256 threads, 4 floats each = 1024
    const float4* xr = reinterpret_cast<const float4*>(x) + (size_t)row * (DIM/4);
    float4 t = xr[tid];
    float s  = t.x + t.y + t.z + t.w;
    float ss = t.x*t.x + t.y*t.y + t.z*t.z + t.w*t.w;
    #pragma unroll
    for (int o = 16; o > 0; o >>= 1) {
        s  += __shfl_xor_sync(0xffffffffu, s,  o);
        ss += __shfl_xor_sync(0xffffffffu, ss, o);
    }
    __shared__ float ws[8], wss[8];
    int w = tid >> 5, l = tid & 31;
    if (l == 0) { ws[w] = s; wss[w] = ss; }
    __syncthreads();
    if (w == 0) {
        float a = (l < 8) ? ws[l]  : 0.f;
        float b = (l < 8) ? wss[l] : 0.f;
        #pragma unroll
        for (int o = 4; o > 0; o >>= 1) {
            a += __shfl_xor_sync(0xffffffffu, a, o);
            b += __shfl_xor_sync(0xffffffffu, b, o);
        }
        if (l == 0) { ws[0] = a; wss[0] = b; }
    }
    __syncthreads();
    float mu  = ws[0]  * (1.f / DIM);
    float var = wss[0] * (1.f / DIM) - mu * mu;
    float r   = rsqrtf(var + 1e-5f);
    float4 gm = reinterpret_cast<const float4*>(gamma)[tid];
    float4 bt = reinterpret_cast<const float4*>(beta)[tid];
    float4 o;
    o.x = (t.x - mu) * r * gm.x + bt.x;
    o.y = (t.y - mu) * r * gm.y + bt.y;
    o.z = (t.z - mu) * r * gm.z + bt.z;
    o.w = (t.w - mu) * r * gm.w + bt.w;
    reinterpret_cast<float4*>(g_h)[(size_t)row * (DIM/4) + tid] = o;
}

// ---------------- TF32 tensor-core GEMM-NT: C[m][n] = sum_k A[m][k]*B[n][k] ----------------
// BM=BN=128, BK=16, 256 threads (8 warps, 2m x 4n), warp tile 64x32 via m16n8k8 TF32 mma.
__device__ __forceinline__ float to_tf32(float x) {
    float r;
    asm("cvt.rna.tf32.f32 %0, %1;" : "=f"(r) : "f"(x));
    return r;
}
__device__ __forceinline__ void mma_tf32(float* d, const uint32_t* a, const uint32_t* b) {
    asm volatile(
        "mma.sync.aligned.m16n8k8.row.col.f32.tf32.tf32.f32 "
        "{%0,%1,%2,%3},{%4,%5,%6,%7},{%8,%9},{%0,%1,%2,%3};"
        : "+f"(d[0]), "+f"(d[1]), "+f"(d[2]), "+f"(d[3])
        : "r"(a[0]), "r"(a[1]), "r"(a[2]), "r"(a[3]), "r"(b[0]), "r"(b[1]));
}

__global__ __launch_bounds__(256) void gemm_nt_tf32(const float* __restrict__ A,
                                                    const float* __restrict__ B,
                                                    float* __restrict__ C,
                                                    int M, int N, int K,
                                                    long strideB, long strideC) {
    __shared__ __align__(16) float As[128 * 20];   // [m][k], pad 20 (conflict-free)
    __shared__ __align__(16) float Bs[128 * 20];   // [n][k]
    const float* Bz = B + (size_t)blockIdx.z * strideB;
    float*       Cz = C + (size_t)blockIdx.z * strideC;
    int m0 = blockIdx.y * 128, n0 = blockIdx.x * 128;
    int tid = threadIdx.x, lane = tid & 31, wid = tid >> 5;
    int wm = (wid & 1) * 64, wn = (wid >> 1) * 32;
    int g = lane >> 2, t = lane & 3;
    float acc[4][4][4] = {};

    for (int k0 = 0; k0 < K; k0 += 16) {
        #pragma unroll
        for (int i = 0; i < 2; i++) {
            int f = tid + 256 * i;          // 0..511
            int r = f >> 2, c4 = f & 3;
            float4 a = *reinterpret_cast<const float4*>(A  + (size_t)(m0 + r) * K + k0 + c4 * 4);
            float* ap = &As[r * 20 + c4 * 4];
            ap[0] = to_tf32(a.x); ap[1] = to_tf32(a.y); ap[2] = to_tf32(a.z); ap[3] = to_tf32(a.w);
            float4 b = *reinterpret_cast<const float4*>(Bz + (size_t)(n0 + r) * K + k0 + c4 * 4);
            float* bp = &Bs[r * 20 + c4 * 4];
            bp[0] = to_tf32(b.x); bp[1] = to_tf32(b.y); bp[2] = to_tf32(b.z); bp[3] = to_tf32(b.w);
        }
        __syncthreads();
        #pragma unroll
        for (int ks = 0; ks < 16; ks += 8) {
            uint32_t aR[4][4], bR[4][2];
            #pragma unroll
            for (int mf = 0; mf < 4; mf++) {
                int mb = wm + mf * 16;
                aR[mf][0] = *reinterpret_cast<uint32_t*>(&As[(mb + g    ) * 20 + ks + t    ]);
                aR[mf][1] = *reinterpret_cast<uint32_t*>(&As[(mb + g + 8) * 20 + ks + t    ]);
                aR[mf][2] = *reinterpret_cast<uint32_t*>(&As[(mb + g    ) * 20 + ks + t + 4]);
                aR[mf][3] = *reinterpret_cast<uint32_t*>(&As[(mb + g + 8) * 20 + ks + t + 4]);
            }
            #pragma unroll
            for (int nf = 0; nf < 4; nf++) {
                int nb = wn + nf * 8;
                bR[nf][0] = *reinterpret_cast<uint32_t*>(&Bs[(nb + g) * 20 + ks + t    ]);
                bR[nf][1] = *reinterpret_cast<uint32_t*>(&Bs[(nb + g) * 20 + ks + t + 4]);
            }
            #pragma unroll
            for (int mf = 0; mf < 4; mf++)
                #pragma unroll
                for (int nf = 0; nf < 4; nf++)
                    mma_tf32(acc[mf][nf], aR[mf], bR[nf]);
        }
        __syncthreads();
    }

    #pragma unroll
    for (int mf = 0; mf < 4; mf++)
        #pragma unroll
        for (int nf = 0; nf < 4; nf++) {
            int m = m0 + wm + mf * 16 + g;
            int n = n0 + wn + nf * 8 + 2 * t;
            float2 v0 = make_float2(acc[mf][nf][0], acc[mf][nf][1]);
            float2 v1 = make_float2(acc[mf][nf][2], acc[mf][nf][3]);
            *reinterpret_cast<float2*>(Cz + (size_t)m * N + n)       = v0;
            *reinterpret_cast<float2*>(Cz + (size_t)(m + 8) * N + n) = v1;
        }
}

// ---------------- depthwise causal conv (channel-major in/out) ----------------
// blockIdx.y selects q/k/v; q applies 1/sqrt(64).
__global__ __launch_bounds__(256) void conv_kernel(
    const float* __restrict__ const* wptr) {
    int p = blockIdx.y;
    int idx = blockIdx.x * 256 + threadIdx.x;     // B*INNER*SEQ threads
    int n = idx & (SEQ - 1);
    int c = (idx >> 11) & (INNER - 1);
    int b = idx >> 21;
    const float* row = g_qkv + ((size_t)b * 3 * INNER + (size_t)p * INNER + c) * SEQ;
    int g = c >> 8, cg = c & 255;
    float acc;
    if (g == 0) {
        acc = row[n];
    } else {
        int ksz = 2 * g + 1;                      // 3,5,7
        const float* w  = wptr[p * 6 + (g - 1) * 2] + cg * ksz;
        const float* bb = wptr[p * 6 + (g - 1) * 2 + 1];
        acc = bb[cg];
        for (int t = 0; t < ksz; t++) {
            int m = n - (ksz - 1) + t;
            if (m >= 0) acc += w[t] * row[m];
        }
    }
    float scale = (p == 0) ? 0.125f : 1.0f;       // 64^-0.5
    float* dst = (p == 0 ? g_q : (p == 1 ? g_k : g_v));
    dst[((size_t)b * INNER + c) * SEQ + n] = acc * scale;
}

__device__ const float* g_convw[18];
__global__ void set_convw(const float* a0, const float* a1, const float* a2, const float* a3,
                          const float* a4, const float* a5, const float* a6, const float* a7,
                          const float* a8, const float* a9, const float* a10, const float* a11,
                          const float* a12, const float* a13, const float* a14, const float* a15,
                          const float* a16, const float* a17) {
    g_convw[0]=a0; g_convw[1]=a1; g_convw[2]=a2; g_convw[3]=a3; g_convw[4]=a4; g_convw[5]=a5;
    g_convw[6]=a6; g_convw[7]=a7; g_convw[8]=a8; g_convw[9]=a9; g_convw[10]=a10; g_convw[11]=a11;
    g_convw[12]=a12; g_convw[13]=a13; g_convw[14]=a14; g_convw[15]=a15; g_convw[16]=a16; g_convw[17]=a17;
}

// ---------------- flash-style causal attention with ALiBi ----------------
// Q/K/V in (B,H,Dh,N) channel-major. 64x64 tiles, 256 threads.
__global__ __launch_bounds__(256) void attn_kernel(const float* __restrict__ slopes) {
    extern __shared__ float sm[];
    float* Qs   = sm;                 // [d][r]  64x68
    float* Ks   = Qs  + 64*68;        // [d][n]
    float* Vs   = Ks  + 64*68;        // [n][d]
    float* Ssm  = Vs  + 64*68;        // [r][n]
    float* Pt   = Ssm + 64*68;        // [n][r]
    float* row_m  = Pt + 64*68;
    float* row_l  = row_m + 64;
    float* row_sc = row_l + 64;

    int it = blockIdx.x; int i0 = it * 64;
    int bh = blockIdx.y; int b = bh >> 4, h = bh & 15;
    float slope = slopes[h];
    int tid = threadIdx.x;
    int ty = tid >> 4, tx = tid & 15;
    const float* Qb = g_q + (size_t)bh * DH * SEQ;
    const float* Kb = g_k + (size_t)bh * DH * SEQ;
    const float* Vb = g_v + (size_t)bh * DH * SEQ;

    #pragma unroll
    for (int i = 0; i < 4; i++) {               // load Q tile (once)
        int f = tid + 256 * i;                  // 0..1023
        int d = f >> 4, c4 = f & 15;
        float4 v = *reinterpret_cast<const float4*>(Qb + (size_t)d * SEQ + i0 + c4 * 4);
        *reinterpret_cast<float4*>(&Qs[d*68 + c4*4]) = v;
    }
    if (tid < 64) { row_m[tid] = -3.4e38f; row_l[tid] = 0.f; }
    float o[4][4] = {};
    __syncthreads();

    for (int jt = 0; jt <= it; jt++) {
        int j0 = jt * 64;
        #pragma unroll
        for (int i = 0; i < 4; i++) {           // load K (direct), V (transposed)
            int f = tid + 256 * i;
            int d = f >> 4, c4 = f & 15;
            float4 kv = *reinterpret_cast<const float4*>(Kb + (size_t)d * SEQ + j0 + c4 * 4);
            *reinterpret_cast<float4*>(&Ks[d*68 + c4*4]) = kv;
            float4 vv = *reinterpret_cast<const float4*>(Vb + (size_t)d * SEQ + j0 + c4 * 4);
            Vs[(c4*4+0)*68 + d] = vv.x;
            Vs[(c4*4+1)*68 + d] = vv.y;
            Vs[(c4*4+2)*68 + d] = vv.z;
            Vs[(c4*4+3)*68 + d] = vv.w;
        }
        __syncthreads();

        float s[4][4] = {};                     // S = Q K^T (outer product over d)
        #pragma unroll 8
        for (int kk = 0; kk < 64; kk++) {
            float4 a  = *reinterpret_cast<float4*>(&Qs[kk*68 + ty*4]);
            float4 bb = *reinterpret_cast<float4*>(&Ks[kk*68 + tx*4]);
            float av[4] = {a.x, a.y, a.z, a.w};
            float bw[4] = {bb.x, bb.y, bb.z, bb.w};
            #pragma unroll
            for (int ii = 0; ii < 4; ii++)
                #pragma unroll
                for (int jj = 0; jj < 4; jj++)
                    s[ii][jj] += av[ii] * bw[jj];
        }
        #pragma unroll
        for (int ii = 0; ii < 4; ii++)
            #pragma unroll
            for (int jj = 0; jj < 4; jj++) {
                int i = i0 + ty*4 + ii, j = j0 + tx*4 + jj;
                float val = s[ii][jj] + slope * (float)(j - i);
                if (j > i) val = -3.4e38f;
                Ssm[(ty*4+ii)*68 + tx*4 + jj] = val;
            }
        __syncthreads();

        {                                       // online softmax: 4 threads per row
            int r = tid >> 2, q = tid & 3;
            float p[16];
            *reinterpret_cast<float4*>(&p[0])  = *reinterpret_cast<float4*>(&Ssm[r*68 + q*16 + 0]);
            *reinterpret_cast<float4*>(&p[4])  = *reinterpret_cast<float4*>(&Ssm[r*68 + q*16 + 4]);
            *reinterpret_cast<float4*>(&p[8])  = *reinterpret_cast<float4*>(&Ssm[r*68 + q*16 + 8]);
            *reinterpret_cast<float4*>(&p[12]) = *reinterpret_cast<float4*>(&Ssm[r*68 + q*16 + 12]);
            float mloc = p[0];
            #pragma unroll
            for (int t = 1; t < 16; t++) mloc = fmaxf(mloc, p[t]);
            mloc = fmaxf(mloc, __shfl_xor_sync(0xffffffffu, mloc, 1));
            mloc = fmaxf(mloc, __shfl_xor_sync(0xffffffffu, mloc, 2));
            float m_old = row_m[r];
            float m_new = fmaxf(m_old, mloc);
            float sum = 0.f;
            #pragma unroll
            for (int t = 0; t < 16; t++) { p[t] = __expf(p[t] - m_new); sum += p[t]; }
            sum += __shfl_xor_sync(0xffffffffu, sum, 1);
            sum += __shfl_xor_sync(0xffffffffu, sum, 2);
            float sc = __expf(m_old - m_new);
            if (q == 0) { row_m[r] = m_new; row_l[r] = row_l[r] * sc + sum; row_sc[r] = sc; }
            #pragma unroll
            for (int t = 0; t < 16; t++) Pt[(q*16 + t)*68 + r] = p[t];
        }
        __syncthreads();

        #pragma unroll
        for (int ii = 0; ii < 4; ii++) {        // rescale accumulators
            float sc = row_sc[ty*4 + ii];
            #pragma unroll
            for (int jj = 0; jj < 4; jj++) o[ii][jj] *= sc;
        }
        #pragma unroll 8
        for (int n = 0; n < 64; n++) {          // O += P V (outer product over n)
            float4 a = *reinterpret_cast<float4*>(&Pt[n*68 + ty*4]);
            float4 v = *reinterpret_cast<float4*>(&Vs[n*68 + tx*4]);
            float av[4] = {a.x, a.y, a.z, a.w};
            float vw[4] = {v.x, v.y, v.z, v.w};
            #pragma unroll
            for (int ii = 0; ii < 4; ii++)
                #pragma unroll
                for (int jj = 0; jj < 4; jj++)
                    o[ii][jj] += av[ii] * vw[jj];
        }
        __syncthreads();
    }

    #pragma unroll
    for (int ii = 0; ii < 4; ii++) {            // normalize + write (B,N,INNER)
        int r = ty*4 + ii;
        float inv = 1.f / row_l[r];
        float4 v = make_float4(o[ii][0]*inv, o[ii][1]*inv, o[ii][2]*inv, o[ii][3]*inv);
        *reinterpret_cast<float4*>(&g_ao[((size_t)b * SEQ + i0 + r) * INNER + h*DH + tx*4]) = v;
    }
}

// ---------------- launch ----------------
extern "C" void kernel_launch(void* const* d_in, const int* in_sizes, int n_in,
                              void* d_out, int out_size) {
    const float* x      = (const float*)d_in[0];
    const float* gamma  = (const float*)d_in[1];
    const float* beta   = (const float*)d_in[2];
    const float* w_qkv  = (const float*)d_in[3];
    const float* slopes = (const float*)d_in[22];
    const float* w_out  = (const float*)d_in[23];

    float *ph, *pqkv, *pao;
    cudaGetSymbolAddress((void**)&ph,   g_h);
    cudaGetSymbolAddress((void**)&pqkv, g_qkv);
    cudaGetSymbolAddress((void**)&pao,  g_ao);
    const float** pconvw;
    cudaGetSymbolAddress((void**)&pconvw, g_convw);

    // 0) stash conv weight pointers (tiny kernel, graph-capturable)
    set_convw<<<1, 1>>>(
        (const float*)d_in[4],  (const float*)d_in[5],  (const float*)d_in[6],
        (const float*)d_in[7],  (const float*)d_in[8],  (const float*)d_in[9],
        (const float*)d_in[10], (const float*)d_in[11], (const float*)d_in[12],
        (const float*)d_in[13], (const float*)d_in[14], (const float*)d_in[15],
        (const float*)d_in[16], (const float*)d_in[17], (const float*)d_in[18],
        (const float*)d_in[19], (const float*)d_in[20], (const float*)d_in[21]);

    // 1) LayerNorm
    ln_kernel<<<BATCH * SEQ, 256>>>(x, gamma, beta);

    // 2) QKV GEMM (TF32 tensor cores): per batch, C(3072 x 2048) = W(3072x1024) . H_b^T
    gemm_nt_tf32<<<dim3(SEQ/128, 3*INNER/128, BATCH), 256>>>(
        w_qkv, ph, pqkv, 3*INNER, SEQ, DIM,
        (long)SEQ * DIM, (long)3 * INNER * SEQ);

    // 3) depthwise causal convs (q scaled by 1/8), one launch, p = blockIdx.y
    int convBlocks = (BATCH * INNER * SEQ) / 256;
    conv_kernel<<<dim3(convBlocks, 3), 256>>>((const float* const*)pconvw);

    // 4) attention
    size_t smem = (size_t)(5 * 64 * 68 + 3 * 64) * sizeof(float);  // 87808 B
    cudaFuncSetAttribute(attn_kernel, cudaFuncAttributeMaxDynamicSharedMemorySize, (int)smem);
    attn_kernel<<<dim3(SEQ/64, BATCH*HEADS), 256, smem>>>(slopes);

    // 5) output projection (TF32): C(4096 x 1024) = AO(4096x1024) . Wout^T
    gemm_nt_tf32<<<dim3(DIM/128, (BATCH*SEQ)/128, 1), 256>>>(
        pao, w_out, (float*)d_out, BATCH*SEQ, DIM, INNER, 0, 0);
}

// round 3
// speedup vs baseline: 2.6090x; 1.7410x over previous
#include <cuda_runtime.h>
#include <math.h>
#include <stdint.h>

#define BATCH 2
#define SEQ   2048
#define DIM   1024
#define HEADS 16
#define DH    64
#define INNER 1024

// ---------------- scratch (device globals; no allocs) ----------------
__device__ float g_h  [BATCH*SEQ*DIM];            // LN output  (B,N,DIM)
__device__ float g_qkv[BATCH*3*INNER*SEQ];        // (B, 3*INNER, SEQ) channel-major
__device__ float g_q  [BATCH*INNER*SEQ];          // (B, INNER, SEQ) channel-major (scaled)
__device__ float g_k  [BATCH*INNER*SEQ];
__device__ float g_v  [BATCH*INNER*SEQ];
__device__ float g_ao [BATCH*SEQ*INNER];          // attention out (B,N,INNER)

// ---------------- LayerNorm ----------------
__global__ __launch_bounds__(256) void ln_kernel(const float* __restrict__ x,
                                                 const float* __restrict__ gamma,
                                                 const float* __restrict__ beta) {
    int row = blockIdx.x;              // 0..B*SEQ-1
    int tid = threadIdx.x;             // 256 threads, 4 floats each = 1024
    const float4* xr = reinterpret_cast<const float4*>(x) + (size_t)row * (DIM/4);
    float4 t = xr[tid];
    float s  = t.x + t.y + t.z + t.w;
    float ss = t.x*t.x + t.y*t.y + t.z*t.z + t.w*t.w;
    #pragma unroll
    for (int o = 16; o > 0; o >>= 1) {
        s  += __shfl_xor_sync(0xffffffffu, s,  o);
        ss += __shfl_xor_sync(0xffffffffu, ss, o);
    }
    __shared__ float ws[8], wss[8];
    int w = tid >> 5, l = tid & 31;
    if (l == 0) { ws[w] = s; wss[w] = ss; }
    __syncthreads();
    if (w == 0) {
        float a = (l < 8) ? ws[l]  : 0.f;
        float b = (l < 8) ? wss[l] : 0.f;
        #pragma unroll
        for (int o = 4; o > 0; o >>= 1) {
            a += __shfl_xor_sync(0xffffffffu, a, o);
            b += __shfl_xor_sync(0xffffffffu, b, o);
        }
        if (l == 0) { ws[0] = a; wss[0] = b; }
    }
    __syncthreads();
    float mu  = ws[0]  * (1.f / DIM);
    float var = wss[0] * (1.f / DIM) - mu * mu;
    float r   = rsqrtf(var + 1e-5f);
    float4 gm = reinterpret_cast<const float4*>(gamma)[tid];
    float4 bt = reinterpret_cast<const float4*>(beta)[tid];
    float4 o;
    o.x = (t.x - mu) * r * gm.x + bt.x;
    o.y = (t.y - mu) * r * gm.y + bt.y;
    o.z = (t.z - mu) * r * gm.z + bt.z;
    o.w = (t.w - mu) * r * gm.w + bt.w;
    reinterpret_cast<float4*>(g_h)[(size_t)row * (DIM/4) + tid] = o;
}

// ---------------- TF32 helpers ----------------
__device__ __forceinline__ float to_tf32(float x) {
    float r;
    asm("cvt.rna.tf32.f32 %0, %1;" : "=f"(r) : "f"(x));
    return r;
}
__device__ __forceinline__ void mma_tf32(float* d, const uint32_t* a, const uint32_t* b) {
    asm volatile(
        "mma.sync.aligned.m16n8k8.row.col.f32.tf32.tf32.f32 "
        "{%0,%1,%2,%3},{%4,%5,%6,%7},{%8,%9},{%0,%1,%2,%3};"
        : "+f"(d[0]), "+f"(d[1]), "+f"(d[2]), "+f"(d[3])
        : "r"(a[0]), "r"(a[1]), "r"(a[2]), "r"(a[3]), "r"(b[0]), "r"(b[1]));
}

// ---------------- TF32 tensor-core GEMM-NT: C[m][n] = sum_k A[m][k]*B[n][k] ----------------
// BM=BN=128, BK=16, 256 threads (8 warps, 2m x 4n), warp tile 64x32 via m16n8k8 TF32 mma.
__global__ __launch_bounds__(256) void gemm_nt_tf32(const float* __restrict__ A,
                                                    const float* __restrict__ B,
                                                    float* __restrict__ C,
                                                    int M, int N, int K,
                                                    long strideB, long strideC) {
    __shared__ __align__(16) float As[128 * 20];   // [m][k], pad 20 (conflict-free)
    __shared__ __align__(16) float Bs[128 * 20];   // [n][k]
    const float* Bz = B + (size_t)blockIdx.z * strideB;
    float*       Cz = C + (size_t)blockIdx.z * strideC;
    int m0 = blockIdx.y * 128, n0 = blockIdx.x * 128;
    int tid = threadIdx.x, lane = tid & 31, wid = tid >> 5;
    int wm = (wid & 1) * 64, wn = (wid >> 1) * 32;
    int g = lane >> 2, t = lane & 3;
    float acc[4][4][4] = {};

    for (int k0 = 0; k0 < K; k0 += 16) {
        #pragma unroll
        for (int i = 0; i < 2; i++) {
            int f = tid + 256 * i;          // 0..511
            int r = f >> 2, c4 = f & 3;
            float4 a = *reinterpret_cast<const float4*>(A  + (size_t)(m0 + r) * K + k0 + c4 * 4);
            float* ap = &As[r * 20 + c4 * 4];
            ap[0] = to_tf32(a.x); ap[1] = to_tf32(a.y); ap[2] = to_tf32(a.z); ap[3] = to_tf32(a.w);
            float4 b = *reinterpret_cast<const float4*>(Bz + (size_t)(n0 + r) * K + k0 + c4 * 4);
            float* bp = &Bs[r * 20 + c4 * 4];
            bp[0] = to_tf32(b.x); bp[1] = to_tf32(b.y); bp[2] = to_tf32(b.z); bp[3] = to_tf32(b.w);
        }
        __syncthreads();
        #pragma unroll
        for (int ks = 0; ks < 16; ks += 8) {
            uint32_t aR[4][4], bR[4][2];
            #pragma unroll
            for (int mf = 0; mf < 4; mf++) {
                int mb = wm + mf * 16;
                aR[mf][0] = *reinterpret_cast<uint32_t*>(&As[(mb + g    ) * 20 + ks + t    ]);
                aR[mf][1] = *reinterpret_cast<uint32_t*>(&As[(mb + g + 8) * 20 + ks + t    ]);
                aR[mf][2] = *reinterpret_cast<uint32_t*>(&As[(mb + g    ) * 20 + ks + t + 4]);
                aR[mf][3] = *reinterpret_cast<uint32_t*>(&As[(mb + g + 8) * 20 + ks + t + 4]);
            }
            #pragma unroll
            for (int nf = 0; nf < 4; nf++) {
                int nb = wn + nf * 8;
                bR[nf][0] = *reinterpret_cast<uint32_t*>(&Bs[(nb + g) * 20 + ks + t    ]);
                bR[nf][1] = *reinterpret_cast<uint32_t*>(&Bs[(nb + g) * 20 + ks + t + 4]);
            }
            #pragma unroll
            for (int mf = 0; mf < 4; mf++)
                #pragma unroll
                for (int nf = 0; nf < 4; nf++)
                    mma_tf32(acc[mf][nf], aR[mf], bR[nf]);
        }
        __syncthreads();
    }

    #pragma unroll
    for (int mf = 0; mf < 4; mf++)
        #pragma unroll
        for (int nf = 0; nf < 4; nf++) {
            int m = m0 + wm + mf * 16 + g;
            int n = n0 + wn + nf * 8 + 2 * t;
            float2 v0 = make_float2(acc[mf][nf][0], acc[mf][nf][1]);
            float2 v1 = make_float2(acc[mf][nf][2], acc[mf][nf][3]);
            *reinterpret_cast<float2*>(Cz + (size_t)m * N + n)       = v0;
            *reinterpret_cast<float2*>(Cz + (size_t)(m + 8) * N + n) = v1;
        }
}

// ---------------- depthwise causal conv (channel-major in/out) ----------------
__global__ __launch_bounds__(256) void conv_kernel(
    const float* __restrict__ const* wptr) {
    int p = blockIdx.y;
    int idx = blockIdx.x * 256 + threadIdx.x;     // B*INNER*SEQ threads
    int n = idx & (SEQ - 1);
    int c = (idx >> 11) & (INNER - 1);
    int b = idx >> 21;
    const float* row = g_qkv + ((size_t)b * 3 * INNER + (size_t)p * INNER + c) * SEQ;
    int g = c >> 8, cg = c & 255;
    float acc;
    if (g == 0) {
        acc = row[n];
    } else {
        int ksz = 2 * g + 1;                      // 3,5,7
        const float* w  = wptr[p * 6 + (g - 1) * 2] + cg * ksz;
        const float* bb = wptr[p * 6 + (g - 1) * 2 + 1];
        acc = bb[cg];
        for (int t = 0; t < ksz; t++) {
            int m = n - (ksz - 1) + t;
            if (m >= 0) acc += w[t] * row[m];
        }
    }
    float scale = (p == 0) ? 0.125f : 1.0f;       // 64^-0.5
    float* dst = (p == 0 ? g_q : (p == 1 ? g_k : g_v));
    dst[((size_t)b * INNER + c) * SEQ + n] = acc * scale;
}

__device__ const float* g_convw[18];
__global__ void set_convw(const float* a0, const float* a1, const float* a2, const float* a3,
                          const float* a4, const float* a5, const float* a6, const float* a7,
                          const float* a8, const float* a9, const float* a10, const float* a11,
                          const float* a12, const float* a13, const float* a14, const float* a15,
                          const float* a16, const float* a17) {
    g_convw[0]=a0; g_convw[1]=a1; g_convw[2]=a2; g_convw[3]=a3; g_convw[4]=a4; g_convw[5]=a5;
    g_convw[6]=a6; g_convw[7]=a7; g_convw[8]=a8; g_convw[9]=a9; g_convw[10]=a10; g_convw[11]=a11;
    g_convw[12]=a12; g_convw[13]=a13; g_convw[14]=a14; g_convw[15]=a15; g_convw[16]=a16; g_convw[17]=a17;
}

// ---------------- tensor-core flash attention (TF32) ----------------
// Q/K/V in (B,H,Dh,N) channel-major. 64 rows/block, 64-col tiles, 128 threads (4 warps).
// All smem tiles stay [d][n] with row stride 72 -> conflict-free frag loads, no transposes.
#define SSTR 72
__global__ __launch_bounds__(128) void attn_tc(const float* __restrict__ slopes) {
    extern __shared__ float sm[];
    float* Ks  = sm;                 // [d][j] 64 x 72
    float* Vs  = Ks + 64*SSTR;       // [d][j]
    float* QPs = Vs + 64*SSTR;       // Q: [d][i], later P: [i][j]

    int it = blockIdx.x, i0 = it * 64;
    int bh = blockIdx.y, b = bh >> 4, h = bh & 15;
    float slope = slopes[h];
    int tid = threadIdx.x, lane = tid & 31, w = tid >> 5;
    int g = lane >> 2, t = lane & 3;
    int mb = w * 16;
    const float* Qb = g_q + (size_t)bh * DH * SEQ;
    const float* Kb = g_k + (size_t)bh * DH * SEQ;
    const float* Vb = g_v + (size_t)bh * DH * SEQ;

    // fill Q tile [d][i] (tf32-converted)
    #pragma unroll
    for (int ii = 0; ii < 8; ii++) {
        int f = tid + 128 * ii, d = f >> 4, c4 = f & 15;
        float4 v = *reinterpret_cast<const float4*>(Qb + (size_t)d * SEQ + i0 + c4 * 4);
        float* p = &QPs[d * SSTR + c4 * 4];
        p[0] = to_tf32(v.x); p[1] = to_tf32(v.y); p[2] = to_tf32(v.z); p[3] = to_tf32(v.w);
    }
    __syncthreads();

    // Q frags (held in registers for the whole j loop)
    uint32_t aQ[8][4];
    #pragma unroll
    for (int ks = 0; ks < 8; ks++) {
        aQ[ks][0] = *reinterpret_cast<uint32_t*>(&QPs[(ks*8 + t    ) * SSTR + mb + g    ]);
        aQ[ks][1] = *reinterpret_cast<uint32_t*>(&QPs[(ks*8 + t    ) * SSTR + mb + g + 8]);
        aQ[ks][2] = *reinterpret_cast<uint32_t*>(&QPs[(ks*8 + t + 4) * SSTR + mb + g    ]);
        aQ[ks][3] = *reinterpret_cast<uint32_t*>(&QPs[(ks*8 + t + 4) * SSTR + mb + g + 8]);
    }

    float o[8][4] = {};
    float m0 = -1e30f, m1 = -1e30f, l0 = 0.f, l1 = 0.f;

    for (int jt = 0; jt <= it; jt++) {
        int j0 = jt * 64;
        __syncthreads();                       // protects QPs(P) WAR + Ks/Vs reuse
        #pragma unroll
        for (int ii = 0; ii < 8; ii++) {       // fill K/V tiles [d][j]
            int f = tid + 128 * ii, d = f >> 4, c4 = f & 15;
            float4 kv = *reinterpret_cast<const float4*>(Kb + (size_t)d * SEQ + j0 + c4 * 4);
            float* p = &Ks[d * SSTR + c4 * 4];
            p[0] = to_tf32(kv.x); p[1] = to_tf32(kv.y); p[2] = to_tf32(kv.z); p[3] = to_tf32(kv.w);
            float4 vv = *reinterpret_cast<const float4*>(Vb + (size_t)d * SEQ + j0 + c4 * 4);
            float* q = &Vs[d * SSTR + c4 * 4];
            q[0] = to_tf32(vv.x); q[1] = to_tf32(vv.y); q[2] = to_tf32(vv.z); q[3] = to_tf32(vv.w);
        }
        __syncthreads();

        // S = Q K^T  (m16 x n64, k=64)
        float sF[8][4] = {};
        #pragma unroll
        for (int ks = 0; ks < 8; ks++) {
            #pragma unroll
            for (int nf = 0; nf < 8; nf++) {
                uint32_t bR[2];
                bR[0] = *reinterpret_cast<uint32_t*>(&Ks[(ks*8 + t    ) * SSTR + nf*8 + g]);
                bR[1] = *reinterpret_cast<uint32_t*>(&Ks[(ks*8 + t + 4) * SSTR + nf*8 + g]);
                mma_tf32(sF[nf], aQ[ks], bR);
            }
        }

        // bias + causal mask + online softmax (rows g / g+8, quad shuffles)
        int ir0 = i0 + mb + g, ir1 = ir0 + 8;
        float mloc0 = -1e30f, mloc1 = -1e30f;
        #pragma unroll
        for (int nf = 0; nf < 8; nf++) {
            int jc = j0 + nf*8 + 2*t;
            float v0 = sF[nf][0] + slope * (float)(jc     - ir0);
            float v1 = sF[nf][1] + slope * (float)(jc + 1 - ir0);
            float v2 = sF[nf][2] + slope * (float)(jc     - ir1);
            float v3 = sF[nf][3] + slope * (float)(jc + 1 - ir1);
            if (jc     > ir0) v0 = -1e30f;
            if (jc + 1 > ir0) v1 = -1e30f;
            if (jc     > ir1) v2 = -1e30f;
            if (jc + 1 > ir1) v3 = -1e30f;
            sF[nf][0] = v0; sF[nf][1] = v1; sF[nf][2] = v2; sF[nf][3] = v3;
            mloc0 = fmaxf(mloc0, fmaxf(v0, v1));
            mloc1 = fmaxf(mloc1, fmaxf(v2, v3));
        }
        mloc0 = fmaxf(mloc0, __shfl_xor_sync(0xffffffffu, mloc0, 1));
        mloc0 = fmaxf(mloc0, __shfl_xor_sync(0xffffffffu, mloc0, 2));
        mloc1 = fmaxf(mloc1, __shfl_xor_sync(0xffffffffu, mloc1, 1));
        mloc1 = fmaxf(mloc1, __shfl_xor_sync(0xffffffffu, mloc1, 2));
        float mn0 = fmaxf(m0, mloc0), mn1 = fmaxf(m1, mloc1);
        float sc0 = __expf(m0 - mn0), sc1 = __expf(m1 - mn1);
        float sum0 = 0.f, sum1 = 0.f;
        #pragma unroll
        for (int nf = 0; nf < 8; nf++) {
            sF[nf][0] = __expf(sF[nf][0] - mn0); sum0 += sF[nf][0];
            sF[nf][1] = __expf(sF[nf][1] - mn0); sum0 += sF[nf][1];
            sF[nf][2] = __expf(sF[nf][2] - mn1); sum1 += sF[nf][2];
            sF[nf][3] = __expf(sF[nf][3] - mn1); sum1 += sF[nf][3];
        }
        sum0 += __shfl_xor_sync(0xffffffffu, sum0, 1);
        sum0 += __shfl_xor_sync(0xffffffffu, sum0, 2);
        sum1 += __shfl_xor_sync(0xffffffffu, sum1, 1);
        sum1 += __shfl_xor_sync(0xffffffffu, sum1, 2);
        l0 = l0 * sc0 + sum0; l1 = l1 * sc1 + sum1;
        m0 = mn0; m1 = mn1;
        #pragma unroll
        for (int nf = 0; nf < 8; nf++) {
            o[nf][0] *= sc0; o[nf][1] *= sc0;
            o[nf][2] *= sc1; o[nf][3] *= sc1;
        }

        // store P (tf32) into QPs rows [mb, mb+16) -- warp-private region
        #pragma unroll
        for (int nf = 0; nf < 8; nf++) {
            *reinterpret_cast<float2*>(&QPs[(mb + g    ) * SSTR + nf*8 + 2*t]) =
                make_float2(to_tf32(sF[nf][0]), to_tf32(sF[nf][1]));
            *reinterpret_cast<float2*>(&QPs[(mb + g + 8) * SSTR + nf*8 + 2*t]) =
                make_float2(to_tf32(sF[nf][2]), to_tf32(sF[nf][3]));
        }
        __syncwarp();

        // O += P V  (m16 x n64(dh), k=64)
        #pragma unroll
        for (int ks = 0; ks < 8; ks++) {
            uint32_t aP[4];
            aP[0] = *reinterpret_cast<uint32_t*>(&QPs[(mb + g    ) * SSTR + ks*8 + t    ]);
            aP[1] = *reinterpret_cast<uint32_t*>(&QPs[(mb + g + 8) * SSTR + ks*8 + t    ]);
            aP[2] = *reinterpret_cast<uint32_t*>(&QPs[(mb + g    ) * SSTR + ks*8 + t + 4]);
            aP[3] = *reinterpret_cast<uint32_t*>(&QPs[(mb + g + 8) * SSTR + ks*8 + t + 4]);
            #pragma unroll
            for (int nf = 0; nf < 8; nf++) {
                uint32_t bR[2];
                bR[0] = *reinterpret_cast<uint32_t*>(&Vs[(nf*8 + g) * SSTR + ks*8 + t    ]);
                bR[1] = *reinterpret_cast<uint32_t*>(&Vs[(nf*8 + g) * SSTR + ks*8 + t + 4]);
                mma_tf32(o[nf], aP, bR);
            }
        }
    }

    // normalize + write (B,N,INNER)
    float inv0 = 1.f / l0, inv1 = 1.f / l1;
    int r0 = i0 + mb + g;
    #pragma unroll
    for (int nf = 0; nf < 8; nf++) {
        int col = h * DH + nf*8 + 2*t;
        *reinterpret_cast<float2*>(&g_ao[((size_t)b * SEQ + r0    ) * INNER + col]) =
            make_float2(o[nf][0] * inv0, o[nf][1] * inv0);
        *reinterpret_cast<float2*>(&g_ao[((size_t)b * SEQ + r0 + 8) * INNER + col]) =
            make_float2(o[nf][2] * inv1, o[nf][3] * inv1);
    }
}

// ---------------- launch ----------------
extern "C" void kernel_launch(void* const* d_in, const int* in_sizes, int n_in,
                              void* d_out, int out_size) {
    const float* x      = (const float*)d_in[0];
    const float* gamma  = (const float*)d_in[1];
    const float* beta   = (const float*)d_in[2];
    const float* w_qkv  = (const float*)d_in[3];
    const float* slopes = (const float*)d_in[22];
    const float* w_out  = (const float*)d_in[23];

    float *ph, *pqkv, *pao;
    cudaGetSymbolAddress((void**)&ph,   g_h);
    cudaGetSymbolAddress((void**)&pqkv, g_qkv);
    cudaGetSymbolAddress((void**)&pao,  g_ao);
    const float** pconvw;
    cudaGetSymbolAddress((void**)&pconvw, g_convw);

    // 0) stash conv weight pointers
    set_convw<<<1, 1>>>(
        (const float*)d_in[4],  (const float*)d_in[5],  (const float*)d_in[6],
        (const float*)d_in[7],  (const float*)d_in[8],  (const float*)d_in[9],
        (const float*)d_in[10], (const float*)d_in[11], (const float*)d_in[12],
        (const float*)d_in[13], (const float*)d_in[14], (const float*)d_in[15],
        (const float*)d_in[16], (const float*)d_in[17], (const float*)d_in[18],
        (const float*)d_in[19], (const float*)d_in[20], (const float*)d_in[21]);

    // 1) LayerNorm
    ln_kernel<<<BATCH * SEQ, 256>>>(x, gamma, beta);

    // 2) QKV GEMM (TF32): per batch, C(3072 x 2048) = W(3072x1024) . H_b^T
    gemm_nt_tf32<<<dim3(SEQ/128, 3*INNER/128, BATCH), 256>>>(
        w_qkv, ph, pqkv, 3*INNER, SEQ, DIM,
        (long)SEQ * DIM, (long)3 * INNER * SEQ);

    // 3) depthwise causal convs (q scaled by 1/8)
    int convBlocks = (BATCH * INNER * SEQ) / 256;
    conv_kernel<<<dim3(convBlocks, 3), 256>>>((const float* const*)pconvw);

    // 4) tensor-core flash attention
    size_t smem = (size_t)(3 * 64 * SSTR) * sizeof(float);  // 55296 B
    cudaFuncSetAttribute(attn_tc, cudaFuncAttributeMaxDynamicSharedMemorySize, (int)smem);
    attn_tc<<<dim3(SEQ/64, BATCH*HEADS), 128, smem>>>(slopes);

    // 5) output projection (TF32): C(4096 x 1024) = AO(4096x1024) . Wout^T
    gemm_nt_tf32<<<dim3(DIM/128, (BATCH*SEQ)/128, 1), 256>>>(
        pao, w_out, (float*)d_out, BATCH*SEQ, DIM, INNER, 0, 0);
}